// round 1
// baseline (speedup 1.0000x reference)
#include <cuda_runtime.h>
#include <cuda_bf16.h>

#define BATCH 256
#define SDIM  1024
#define NOFF  36                 // 6x6 window, offsets -3..2
#define NTOT  (BATCH * NOFF)     // 9216
#define NTHREADS 1024

__global__ __launch_bounds__(NTHREADS, 1)
void loss_39934605918651_kernel(const float* __restrict__ y_predict,
                                const int*   __restrict__ gt_pos,
                                float*       __restrict__ out) {
    __shared__ int sgx[BATCH];
    __shared__ int sgy[BATCH];
    __shared__ unsigned long long sSx, sSy, sSxx, sSyy;
    __shared__ float wacc[32];
    __shared__ int   wcnt[32];

    const int tid  = threadIdx.x;
    const int lane = tid & 31;
    const int wid  = tid >> 5;

    if (tid == 0) { sSx = 0ull; sSy = 0ull; sSxx = 0ull; sSyy = 0ull; }
    __syncthreads();

    // Load gt_pos and accumulate moment sums (exact in int64).
    if (tid < BATCH) {
        int gx = gt_pos[2 * tid];
        int gy = gt_pos[2 * tid + 1];
        sgx[tid] = gx;
        sgy[tid] = gy;
        // warp-local partial sums to cut shared-atomic contention
        unsigned long long x = (unsigned long long)gx;
        unsigned long long y = (unsigned long long)gy;
        unsigned long long xx = (unsigned long long)((long long)gx * gx);
        unsigned long long yy = (unsigned long long)((long long)gy * gy);
        #pragma unroll
        for (int off = 16; off; off >>= 1) {
            x  += __shfl_down_sync(0xFFFFFFFFu, x,  off);
            y  += __shfl_down_sync(0xFFFFFFFFu, y,  off);
            xx += __shfl_down_sync(0xFFFFFFFFu, xx, off);
            yy += __shfl_down_sync(0xFFFFFFFFu, yy, off);
        }
        if (lane == 0) {
            atomicAdd(&sSx,  x);
            atomicAdd(&sSy,  y);
            atomicAdd(&sSxx, xx);
            atomicAdd(&sSyy, yy);
        }
    }
    __syncthreads();

    const long long Sx  = (long long)sSx;
    const long long Sy  = (long long)sSy;
    const long long Sc  = (long long)sSxx + (long long)sSyy;

    float acc = 0.0f;
    int   cnt = 0;

    #pragma unroll
    for (int i = tid; i < NTOT; i += NTHREADS) {
        int b  = i / NOFF;
        int o  = i - b * NOFF;
        int oi = o / 6 - 3;
        int oj = o - (o / 6) * 6 - 3;

        int gx = sgx[b];
        int gy = sgy[b];
        int px = gx + oi;
        int py = gy + oj;

        bool valid = (px >= 0) & (px < SDIM) & (py >= 0) & (py < SDIM);
        int pcx = min(max(px, 0), SDIM - 1);
        int pcy = min(max(py, 0), SDIM - 1);

        float y_hat = __ldg(&y_predict[(size_t)b * (SDIM * SDIM)
                                       + (size_t)pcx * SDIM + pcy]);

        // sq = B*(px^2+py^2) - 2*(px*Sx + py*Sy) + (Sxx + Syy), exact int64
        long long sq_i = (long long)BATCH * ((long long)px * px + (long long)py * py)
                       - 2ll * ((long long)px * Sx + (long long)py * Sy)
                       + Sc;
        float sq = (float)sq_i;
        float y  = __expf(-sq * 0.2f);   // underflows to 0.0f for sq > ~440 (matches ref fp32)
        float d  = y_hat - y;
        float term;
        if (y == 1.0f) {
            term = -__logf(y_hat) * d * d;
        } else {
            float omy = 1.0f - y;
            float w2  = omy * omy;
            term = -__logf(1.0f - y_hat) * (w2 * w2) * d * d;
        }
        if (valid) { acc += term; cnt += 1; }
    }

    // Block reduction: warp shuffle then shared.
    #pragma unroll
    for (int off = 16; off; off >>= 1) {
        acc += __shfl_down_sync(0xFFFFFFFFu, acc, off);
        cnt += __shfl_down_sync(0xFFFFFFFFu, cnt, off);
    }
    if (lane == 0) { wacc[wid] = acc; wcnt[wid] = cnt; }
    __syncthreads();

    if (wid == 0) {
        acc = wacc[lane];
        cnt = wcnt[lane];
        #pragma unroll
        for (int off = 16; off; off >>= 1) {
            acc += __shfl_down_sync(0xFFFFFFFFu, acc, off);
            cnt += __shfl_down_sync(0xFFFFFFFFu, cnt, off);
        }
        if (lane == 0) {
            out[0] = acc / (float)cnt;
        }
    }
}

extern "C" void kernel_launch(void* const* d_in, const int* in_sizes, int n_in,
                              void* d_out, int out_size) {
    const float* y_predict = (const float*)d_in[0];
    const int*   gt_pos    = (const int*)d_in[1];
    float*       out       = (float*)d_out;
    loss_39934605918651_kernel<<<1, NTHREADS>>>(y_predict, gt_pos, out);
}

// round 2
// speedup vs baseline: 1.2657x; 1.2657x over previous
#include <cuda_runtime.h>
#include <cuda_bf16.h>

#define BATCH 256
#define SDIM  1024
#define NOFF  36
#define NTHREADS 64
#define FP_SCALE 274877906944.0f       // 2^38
#define FP_INV   (1.0 / 274877906944.0)

__device__ unsigned long long gAcc;    // fixed-point sum, zero-init; reset after use
__device__ int gCnt;                   // valid count
__device__ int gTicket;                // completion ticket

__global__ __launch_bounds__(NTHREADS, 16)
void loss_39934605918651_kernel(const float* __restrict__ y_predict,
                                const int*   __restrict__ gt_pos,
                                float*       __restrict__ out) {
    const int b    = blockIdx.x;
    const int t    = threadIdx.x;
    const int lane = t & 31;
    const int w    = t >> 5;

    __shared__ int   smom[8];     // 2 warps x {sx, sy, sxx, syy}
    __shared__ float sterm[2];
    __shared__ int   scnt[2];

    // Dependent hop 1: this batch's gt position (broadcast load).
    const int gx = __ldg(&gt_pos[2 * b]);
    const int gy = __ldg(&gt_pos[2 * b + 1]);

    // Independent: moment partial sums over all 256 gt positions (4 pairs/thread).
    const int2* g2 = (const int2*)gt_pos;
    int sx = 0, sy = 0, sxx = 0, syy = 0;
    #pragma unroll
    for (int k = 0; k < 4; k++) {
        int2 p = __ldg(&g2[t + NTHREADS * k]);
        sx  += p.x;       sy  += p.y;
        sxx += p.x * p.x; syy += p.y * p.y;
    }

    // Dependent hop 2: the gather (threads 0..35 active).
    const int  q    = t / 6;
    const int  oi   = q - 3;
    const int  oj   = t - q * 6 - 3;
    const int  px   = gx + oi;
    const int  py   = gy + oj;
    const bool act  = (t < NOFF);
    const bool valid = act & (px >= 0) & (px < SDIM) & (py >= 0) & (py < SDIM);
    const int  pcx  = min(max(px, 0), SDIM - 1);
    const int  pcy  = min(max(py, 0), SDIM - 1);
    float y_hat = 0.5f;
    if (act)
        y_hat = __ldg(&y_predict[((size_t)b << 20) + ((size_t)pcx << 10) + pcy]);

    // Reduce moments across the CTA (overlaps with gather latency).
    #pragma unroll
    for (int o = 16; o; o >>= 1) {
        sx  += __shfl_down_sync(0xFFFFFFFFu, sx,  o);
        sy  += __shfl_down_sync(0xFFFFFFFFu, sy,  o);
        sxx += __shfl_down_sync(0xFFFFFFFFu, sxx, o);
        syy += __shfl_down_sync(0xFFFFFFFFu, syy, o);
    }
    if (lane == 0) {
        smom[w * 4 + 0] = sx;  smom[w * 4 + 1] = sy;
        smom[w * 4 + 2] = sxx; smom[w * 4 + 3] = syy;
    }
    __syncthreads();
    const int Sx = smom[0] + smom[4];
    const int Sy = smom[1] + smom[5];
    const int Sc = smom[2] + smom[6] + smom[3] + smom[7];

    // sq = B*(px^2+py^2) - 2*(px*Sx + py*Sy) + (Sxx+Syy); fits in int32.
    const int sq_i = BATCH * (px * px + py * py) - 2 * (px * Sx + py * Sy) + Sc;
    const float sq = (float)sq_i;
    const float y  = __expf(-sq * 0.2f);   // underflows to 0 exactly like the fp32 ref
    const float d  = y_hat - y;
    float term;
    if (y == 1.0f) {
        term = -__logf(y_hat) * d * d;
    } else {
        const float omy = 1.0f - y;
        const float w2  = omy * omy;
        term = -__logf(1.0f - y_hat) * (w2 * w2) * d * d;
    }
    float tv = valid ? term : 0.0f;
    int   cv = valid ? 1 : 0;

    // CTA reduction.
    #pragma unroll
    for (int o = 16; o; o >>= 1) {
        tv += __shfl_down_sync(0xFFFFFFFFu, tv, o);
        cv += __shfl_down_sync(0xFFFFFFFFu, cv, o);
    }
    if (lane == 0) { sterm[w] = tv; scnt[w] = cv; }
    __syncthreads();

    if (t == 0) {
        const float ctaTerm = sterm[0] + sterm[1];
        const int   ctaCnt  = scnt[0] + scnt[1];
        const long long fp  = __float2ll_rn(ctaTerm * FP_SCALE);  // terms are >= 0
        atomicAdd(&gAcc, (unsigned long long)fp);
        atomicAdd(&gCnt, ctaCnt);
        __threadfence();
        const int ticket = atomicAdd(&gTicket, 1);
        if (ticket == BATCH - 1) {
            const unsigned long long a = atomicAdd(&gAcc, 0ULL);
            const int                c = atomicAdd(&gCnt, 0);
            out[0] = (float)((double)(long long)a * FP_INV / (double)c);
            // Reset for the next graph replay (deterministic across calls).
            gAcc = 0ULL; gCnt = 0; gTicket = 0;
        }
    }
}

extern "C" void kernel_launch(void* const* d_in, const int* in_sizes, int n_in,
                              void* d_out, int out_size) {
    const float* y_predict = (const float*)d_in[0];
    const int*   gt_pos    = (const int*)d_in[1];
    float*       out       = (float*)d_out;
    loss_39934605918651_kernel<<<BATCH, NTHREADS>>>(y_predict, gt_pos, out);
}

// round 3
// speedup vs baseline: 1.6490x; 1.3029x over previous
#include <cuda_runtime.h>
#include <cuda_bf16.h>

#define BATCH 256
#define SDIM  1024
#define NOFF  36
#define FP_SCALE 131072.0f      // 2^17

// Packed accumulator: [63:54] CTA arrivals, [53:14] fixed-point sum, [13:0] count.
__device__ unsigned long long gPack;   // zero-initialized; reset by last CTA each call

__global__ __launch_bounds__(32, 32)
void loss_39934605918651_kernel(const float* __restrict__ y_predict,
                                const int*   __restrict__ gt_pos,
                                float*       __restrict__ out) {
    const int b = blockIdx.x;
    const int t = threadIdx.x;

    // Each lane loads 8 gt pairs -> warp covers all 256 batches.
    const int2* g2 = (const int2*)gt_pos;
    int2 p[8];
    #pragma unroll
    for (int k = 0; k < 8; k++) p[k] = __ldg(&g2[t + 32 * k]);

    // Moment partials.
    int sx = 0, sy = 0, scc = 0;
    #pragma unroll
    for (int k = 0; k < 8; k++) {
        sx  += p[k].x;
        sy  += p[k].y;
        scc += p[k].x * p[k].x + p[k].y * p[k].y;
    }

    // This CTA's own gt position: predicated select of reg k = b>>5, then shuffle from lane b&31.
    const int kown = b >> 5;
    int gxl = p[0].x, gyl = p[0].y;
    #pragma unroll
    for (int k = 1; k < 8; k++) {
        if (kown == k) { gxl = p[k].x; gyl = p[k].y; }
    }
    const int gx = __shfl_sync(0xFFFFFFFFu, gxl, b & 31);
    const int gy = __shfl_sync(0xFFFFFFFFu, gyl, b & 31);

    // Warp-wide exact moment sums (single REDUX each).
    const int Sx = __reduce_add_sync(0xFFFFFFFFu, sx);
    const int Sy = __reduce_add_sync(0xFFFFFFFFu, sy);
    const int Sc = __reduce_add_sync(0xFFFFFFFFu, scc);

    int fpsum = 0, cnt = 0;

    #pragma unroll
    for (int i = t; i < NOFF; i += 32) {
        const int q  = i / 6;
        const int oi = q - 3;
        const int oj = i - q * 6 - 3;
        const int px = gx + oi;
        const int py = gy + oj;

        const bool valid = (px >= 0) & (px < SDIM) & (py >= 0) & (py < SDIM);
        const int pcx = min(max(px, 0), SDIM - 1);
        const int pcy = min(max(py, 0), SDIM - 1);

        const float y_hat = __ldg(&y_predict[((size_t)b << 20) + ((size_t)pcx << 10) + pcy]);

        // sq = B*(px^2+py^2) - 2*(px*Sx + py*Sy) + Sc, exact in int32.
        const int   sq_i = BATCH * (px * px + py * py) - 2 * (px * Sx + py * Sy) + Sc;
        const float sq   = (float)sq_i;
        const float y    = __expf(-sq * 0.2f);   // underflows to 0 exactly like fp32 ref
        const float d    = y_hat - y;
        float term;
        if (y == 1.0f) {
            term = -__logf(y_hat) * d * d;
        } else {
            const float omy = 1.0f - y;
            const float w2  = omy * omy;
            term = -__logf(1.0f - y_hat) * (w2 * w2) * d * d;
        }
        if (valid) {
            fpsum += __float2int_rn(term * FP_SCALE);   // term >= 0
            cnt   += 1;
        }
    }

    // Exact, order-independent warp reduction.
    fpsum = __reduce_add_sync(0xFFFFFFFFu, fpsum);
    cnt   = __reduce_add_sync(0xFFFFFFFFu, cnt);

    if (t == 0) {
        const unsigned long long mine =
            (1ULL << 54) | ((unsigned long long)(unsigned int)fpsum << 14)
                         | (unsigned long long)cnt;
        const unsigned long long old = atomicAdd(&gPack, mine);
        if ((old >> 54) == (unsigned long long)(BATCH - 1)) {
            const unsigned long long tot = old + mine;   // complete total, no readback
            const long long fp = (long long)((tot >> 14) & ((1ULL << 40) - 1));
            const int       c  = (int)(tot & 0x3FFFULL);
            out[0] = (float)(((double)fp / (double)FP_SCALE) / (double)c);
            atomicExch(&gPack, 0ULL);                    // reset for next graph replay
        }
    }
}

extern "C" void kernel_launch(void* const* d_in, const int* in_sizes, int n_in,
                              void* d_out, int out_size) {
    const float* y_predict = (const float*)d_in[0];
    const int*   gt_pos    = (const int*)d_in[1];
    float*       out       = (float*)d_out;
    loss_39934605918651_kernel<<<BATCH, 32>>>(y_predict, gt_pos, out);
}